// round 10
// baseline (speedup 1.0000x reference)
#include <cuda_runtime.h>
#include <cuda_fp16.h>
#include <mma.h>
using namespace nvcuda;

#define NN 100000
#define NE 1600000
#define NG 64

// ---------------- scratch (device globals) ---------------------------------
__device__ float   g_dinv[NN];
__device__ int     g_deg[NN];
__device__ int     g_rowptr[NN];
__device__ int     g_cursor[NN];
__device__ int     g_bsum[128];
__device__ int     g_csr[NE];
__device__ __half2 g_h1p[(size_t)NN * 64];   // fp16: dinv * (x W1), 128 feat
__device__ float   g_h1 [(size_t)NN * 128];  // fp32: post agg+relu (gemm2 in)
__device__ __half2 g_h2p[(size_t)NN * 32];   // fp16: dinv * (h1 W2), 64 feat
__device__ float   g_gsum[NG * 64];
__device__ float   g_gcnt[NG];

__device__ __forceinline__ void red_add_v4(float* p, float4 v) {
    asm volatile("red.global.add.v4.f32 [%0], {%1, %2, %3, %4};"
                 :: "l"(p), "f"(v.x), "f"(v.y), "f"(v.z), "f"(v.w)
                 : "memory");
}
__device__ __forceinline__ float2 h2f(float raw) {
    return __half22float2(*reinterpret_cast<__half2*>(&raw));
}

// ---------------- init ------------------------------------------------------
__global__ void k_init(int n) {
    int i = blockIdx.x * blockDim.x + threadIdx.x;
    if (i < n)       g_deg[i] = 0;
    if (i < NG * 64) g_gsum[i] = 0.0f;
    if (i < NG)      g_gcnt[i] = 0.0f;
}

// ---------------- degree histogram over dst --------------------------------
__global__ void k_hist(const int* __restrict__ dst, int E) {
    int e = blockIdx.x * blockDim.x + threadIdx.x;
    if (e < E) atomicAdd(&g_deg[dst[e]], 1);
}

// ---------------- scan step 1: per-block (1024) scan -----------------------
__global__ void k_scan1(int n) {
    __shared__ int sh[1024];
    int tid = threadIdx.x;
    int i = blockIdx.x * 1024 + tid;
    int v = (i < n) ? g_deg[i] : 0;
    sh[tid] = v;
    __syncthreads();
#pragma unroll
    for (int off = 1; off < 1024; off <<= 1) {
        int t = (tid >= off) ? sh[tid - off] : 0;
        __syncthreads();
        sh[tid] += t;
        __syncthreads();
    }
    if (i < n) g_rowptr[i] = sh[tid] - v;          // exclusive
    if (tid == 1023) g_bsum[blockIdx.x] = sh[1023];
}

// ---------------- scan step 2: warp-shuffle scan of block sums -------------
__global__ void k_scan2(int nb) {
    int lane = threadIdx.x;   // 32 threads
    int carry = 0;
    for (int base = 0; base < nb; base += 32) {
        int idx = base + lane;
        int orig = (idx < nb) ? g_bsum[idx] : 0;
        int v = orig;
#pragma unroll
        for (int off = 1; off < 32; off <<= 1) {
            int u = __shfl_up_sync(0xFFFFFFFFu, v, off);
            if (lane >= off) v += u;
        }
        if (idx < nb) g_bsum[idx] = v - orig + carry;   // exclusive + carry
        carry += __shfl_sync(0xFFFFFFFFu, v, 31);
    }
}

// ---------------- scan step 3: offsets, cursor, dinv, graph counts ---------
__global__ void k_scan3(const int* __restrict__ batch, int n) {
    int i = blockIdx.x * blockDim.x + threadIdx.x;
    if (i < n) {
        int r = g_rowptr[i] + g_bsum[i >> 10];
        g_rowptr[i] = r;
        g_cursor[i] = r;
        g_dinv[i]   = rsqrtf((float)g_deg[i] + 1.0f);   // +1 self loop
        atomicAdd(&g_gcnt[batch[i]], 1.0f);
    }
}

// ---------------- CSR scatter ----------------------------------------------
__global__ void k_scatter(const int* __restrict__ src,
                          const int* __restrict__ dst, int E) {
    int e = blockIdx.x * blockDim.x + threadIdx.x;
    if (e < E) {
        int pos = atomicAdd(&g_cursor[dst[e]], 1);
        g_csr[pos] = src[e];
    }
}

// ---------------- 3xTF32 GEMM (register-lean): C = fp16((dinv*A) @ W) ------
// A hi/lo split PRE-COMPUTED in smem; B split per-fragment on the fly.
// LAYER 1: A = x, C = g_h1p, BN = 128.  LAYER 2: A = g_h1, C = g_h2p, BN = 64.
template <int LAYER>
__global__ void k_gemm(const float* __restrict__ Ain,
                       const float* __restrict__ W, int M) {
    constexpr int BN  = (LAYER == 1) ? 128 : 64;
    constexpr int K   = 128;
    constexpr int KC  = 16;
    constexpr int LDA = KC + 8;                 // 24, multiple of 4
    constexpr int LDB = BN + 8;                 // 136 / 72, multiple of 4
    constexpr int WN  = BN / 2;                 // 64 or 32
    constexpr int NF  = WN / 16;                // 4 or 2
    const float* __restrict__ A = (LAYER == 1) ? Ain : g_h1;
    __half2* __restrict__     C = (LAYER == 1) ? g_h1p : g_h2p;
    constexpr int CH2 = BN / 2;

    __shared__ __align__(16) float AsH[128][LDA];
    __shared__ __align__(16) float AsL[128][LDA];
    __shared__ __align__(16) float Bs [KC][LDB];

    const int t    = threadIdx.x;
    const int wid  = t >> 5;
    const int lane = t & 31;
    const int mbase = blockIdx.x * 128;
    const int wm = (wid >> 1) * 32;
    const int wn = (wid & 1) * WN;

    wmma::fragment<wmma::accumulator, 16, 16, 8, float> c[2][NF];
#pragma unroll
    for (int i = 0; i < 2; i++)
#pragma unroll
        for (int j = 0; j < NF; j++) wmma::fill_fragment(c[i][j], 0.0f);

    for (int k0 = 0; k0 < K; k0 += KC) {
        // A tile: 128 x 16 floats = 512 float4, 2/thread; split hi/lo here
#pragma unroll
        for (int j = 0; j < 2; j++) {
            int idx = t + j * 256;
            int row = idx >> 2;
            int kq  = (idx & 3) << 2;
            float4 av = make_float4(0.f, 0.f, 0.f, 0.f);
            float  s  = 0.0f;
            if (mbase + row < M) {
                av = *reinterpret_cast<const float4*>(
                    A + (size_t)(mbase + row) * K + k0 + kq);
                s = g_dinv[mbase + row];
            }
            float v0 = s * av.x, v1 = s * av.y, v2 = s * av.z, v3 = s * av.w;
            float h0 = wmma::__float_to_tf32(v0);
            float h1v = wmma::__float_to_tf32(v1);
            float h2v = wmma::__float_to_tf32(v2);
            float h3 = wmma::__float_to_tf32(v3);
            AsH[row][kq + 0] = h0;  AsL[row][kq + 0] = wmma::__float_to_tf32(v0 - h0);
            AsH[row][kq + 1] = h1v; AsL[row][kq + 1] = wmma::__float_to_tf32(v1 - h1v);
            AsH[row][kq + 2] = h2v; AsL[row][kq + 2] = wmma::__float_to_tf32(v2 - h2v);
            AsH[row][kq + 3] = h3;  AsL[row][kq + 3] = wmma::__float_to_tf32(v3 - h3);
        }
        // B tile: KC x BN floats (raw fp32)
        constexpr int B4  = KC * BN / 4;        // 512 or 256
#pragma unroll
        for (int j = 0; j < (B4 + 255) / 256; j++) {
            int idx = t + j * 256;
            if (idx < B4) {
                int row = idx / (BN / 4);
                int col = (idx % (BN / 4)) << 2;
                float4 bv = *reinterpret_cast<const float4*>(
                    W + (size_t)(k0 + row) * BN + col);
                Bs[row][col + 0] = bv.x;
                Bs[row][col + 1] = bv.y;
                Bs[row][col + 2] = bv.z;
                Bs[row][col + 3] = bv.w;
            }
        }
        __syncthreads();

#pragma unroll
        for (int kk = 0; kk < KC; kk += 8) {
            wmma::fragment<wmma::matrix_a, 16, 16, 8, wmma::precision::tf32, wmma::row_major> aH[2], aL[2];
#pragma unroll
            for (int i = 0; i < 2; i++) {
                wmma::load_matrix_sync(aH[i], &AsH[wm + i * 16][kk], LDA);
                wmma::load_matrix_sync(aL[i], &AsL[wm + i * 16][kk], LDA);
            }
#pragma unroll
            for (int j = 0; j < NF; j++) {
                wmma::fragment<wmma::matrix_b, 16, 16, 8, wmma::precision::tf32, wmma::row_major> bH, bL;
                wmma::load_matrix_sync(bH, &Bs[kk][wn + j * 16], LDB);
#pragma unroll
                for (int e = 0; e < bH.num_elements; e++) {
                    float v  = bH.x[e];
                    float hi = wmma::__float_to_tf32(v);
                    bH.x[e] = hi;
                    bL.x[e] = wmma::__float_to_tf32(v - hi);
                }
#pragma unroll
                for (int i = 0; i < 2; i++) {
                    wmma::mma_sync(c[i][j], aL[i], bH, c[i][j]);
                    wmma::mma_sync(c[i][j], aH[i], bL, c[i][j]);
                    wmma::mma_sync(c[i][j], aH[i], bH, c[i][j]);
                }
            }
        }
        __syncthreads();
    }

    // epilogue: reuse AsH as per-warp stage (16x20 floats each), emit half2
    float* stg = &AsH[0][0] + wid * 320;
#pragma unroll
    for (int i = 0; i < 2; i++)
#pragma unroll
        for (int j = 0; j < NF; j++) {
            wmma::store_matrix_sync(stg, c[i][j], 20, wmma::mem_row_major);
            __syncwarp();
#pragma unroll
            for (int it = 0; it < 4; it++) {
                int idx = lane + it * 32;            // 0..127
                int rr  = idx >> 3;                  // 0..15
                int cp  = idx & 7;                   // half2 col pair
                int m = mbase + wm + i * 16 + rr;
                if (m < M) {
                    __half2 hv = __floats2half2_rn(stg[rr * 20 + cp * 2],
                                                   stg[rr * 20 + cp * 2 + 1]);
                    C[(size_t)m * CH2 + wn / 2 + j * 8 + cp] = hv;
                }
            }
            __syncwarp();
        }
}

// ---------------- agg layer 1 (D=128): warp/node, fp16 gather, MLP=8 -------
__global__ void k_agg1(const float* __restrict__ b1, int N) {
    int w = (blockIdx.x * blockDim.x + threadIdx.x) >> 5;
    if (w >= N) return;
    int lane = threadIdx.x & 31;
    const float2* H = (const float2*)g_h1p;   // 32 float2 per row (=4 halves)

    int start = g_rowptr[w];
    int cnt   = g_deg[w];

    float2 raw = __ldg(H + (size_t)w * 32 + lane);    // self term
    float2 p0 = h2f(raw.x), p1 = h2f(raw.y);
    float4 acc = make_float4(p0.x, p0.y, p1.x, p1.y);

    int j = 0;
    for (; j + 8 <= cnt; j += 8) {
        int s[8]; float2 r[8];
#pragma unroll
        for (int q = 0; q < 8; q++) s[q] = __ldg(g_csr + start + j + q);
#pragma unroll
        for (int q = 0; q < 8; q++) r[q] = __ldg(H + (size_t)s[q] * 32 + lane);
#pragma unroll
        for (int q = 0; q < 8; q++) {
            float2 a0 = h2f(r[q].x), a1 = h2f(r[q].y);
            acc.x += a0.x; acc.y += a0.y; acc.z += a1.x; acc.w += a1.y;
        }
    }
    if (j + 4 <= cnt) {
        int s[4]; float2 r[4];
#pragma unroll
        for (int q = 0; q < 4; q++) s[q] = __ldg(g_csr + start + j + q);
#pragma unroll
        for (int q = 0; q < 4; q++) r[q] = __ldg(H + (size_t)s[q] * 32 + lane);
#pragma unroll
        for (int q = 0; q < 4; q++) {
            float2 a0 = h2f(r[q].x), a1 = h2f(r[q].y);
            acc.x += a0.x; acc.y += a0.y; acc.z += a1.x; acc.w += a1.y;
        }
        j += 4;
    }
    for (; j < cnt; j++) {
        int s = __ldg(g_csr + start + j);
        float2 r = __ldg(H + (size_t)s * 32 + lane);
        float2 a0 = h2f(r.x), a1 = h2f(r.y);
        acc.x += a0.x; acc.y += a0.y; acc.z += a1.x; acc.w += a1.y;
    }
    float di = g_dinv[w];
    float4 bb = __ldg((const float4*)b1 + lane);
    acc.x = fmaxf(di * acc.x + bb.x, 0.0f);
    acc.y = fmaxf(di * acc.y + bb.y, 0.0f);
    acc.z = fmaxf(di * acc.z + bb.z, 0.0f);
    acc.w = fmaxf(di * acc.w + bb.w, 0.0f);
    ((float4*)g_h1)[(size_t)w * 32 + lane] = acc;
}

// ---------------- agg layer 2 (D=64)+pool: 16 thr/node, fp16, MLP=8 --------
__global__ void k_agg2(const int* __restrict__ batch,
                       const float* __restrict__ b2, int N) {
    int idx = blockIdx.x * blockDim.x + threadIdx.x;
    int node = idx >> 4;
    if (node >= N) return;
    int f4 = idx & 15;
    const float2* H = (const float2*)g_h2p;   // 16 float2 per row

    int start = g_rowptr[node];
    int cnt   = g_deg[node];

    float2 raw = __ldg(H + (size_t)node * 16 + f4);   // self term
    float2 p0 = h2f(raw.x), p1 = h2f(raw.y);
    float4 acc = make_float4(p0.x, p0.y, p1.x, p1.y);

    int j = 0;
    for (; j + 8 <= cnt; j += 8) {
        int s[8]; float2 r[8];
#pragma unroll
        for (int q = 0; q < 8; q++) s[q] = __ldg(g_csr + start + j + q);
#pragma unroll
        for (int q = 0; q < 8; q++) r[q] = __ldg(H + (size_t)s[q] * 16 + f4);
#pragma unroll
        for (int q = 0; q < 8; q++) {
            float2 a0 = h2f(r[q].x), a1 = h2f(r[q].y);
            acc.x += a0.x; acc.y += a0.y; acc.z += a1.x; acc.w += a1.y;
        }
    }
    if (j + 4 <= cnt) {
        int s[4]; float2 r[4];
#pragma unroll
        for (int q = 0; q < 4; q++) s[q] = __ldg(g_csr + start + j + q);
#pragma unroll
        for (int q = 0; q < 4; q++) r[q] = __ldg(H + (size_t)s[q] * 16 + f4);
#pragma unroll
        for (int q = 0; q < 4; q++) {
            float2 a0 = h2f(r[q].x), a1 = h2f(r[q].y);
            acc.x += a0.x; acc.y += a0.y; acc.z += a1.x; acc.w += a1.y;
        }
        j += 4;
    }
    for (; j < cnt; j++) {
        int s = __ldg(g_csr + start + j);
        float2 r = __ldg(H + (size_t)s * 16 + f4);
        float2 a0 = h2f(r.x), a1 = h2f(r.y);
        acc.x += a0.x; acc.y += a0.y; acc.z += a1.x; acc.w += a1.y;
    }
    float di = g_dinv[node];
    float4 bb = __ldg((const float4*)b2 + f4);
    acc.x = fmaxf(di * acc.x + bb.x, 0.0f);
    acc.y = fmaxf(di * acc.y + bb.y, 0.0f);
    acc.z = fmaxf(di * acc.z + bb.z, 0.0f);
    acc.w = fmaxf(di * acc.w + bb.w, 0.0f);

    int g = __ldg(batch + node);
    red_add_v4(&g_gsum[(g << 6) + (f4 << 2)], acc);
}

// ---------------- mean -----------------------------------------------------
__global__ void k_final(float* __restrict__ out) {
    int i = blockIdx.x * blockDim.x + threadIdx.x;
    if (i < NG * 64) out[i] = g_gsum[i] / fmaxf(g_gcnt[i >> 6], 1.0f);
}

// ===========================================================================
extern "C" void kernel_launch(void* const* d_in, const int* in_sizes, int n_in,
                              void* d_out, int out_size) {
    const float* x     = (const float*)d_in[0];
    const int*   ei    = (const int*)d_in[1];
    const int*   batch = (const int*)d_in[2];
    const float* W1    = (const float*)d_in[3];
    const float* b1    = (const float*)d_in[4];
    const float* W2    = (const float*)d_in[5];
    const float* b2    = (const float*)d_in[6];
    float*       out   = (float*)d_out;

    const int N = in_sizes[2];        // 100000
    const int E = in_sizes[1] / 2;    // 1600000
    const int* src = ei;
    const int* dst = ei + E;

    const int TB = 256;
    int nb_N  = (N + TB - 1) / TB;
    int nb_E  = (E + TB - 1) / TB;
    int nb_sc = (N + 1023) / 1024;    // scan blocks

    // graph prep: degree, rowptr, csr, dinv, graph counts
    k_init   <<<nb_N, TB>>>(N);
    k_hist   <<<nb_E, TB>>>(dst, E);
    k_scan1  <<<nb_sc, 1024>>>(N);
    k_scan2  <<<1, 32>>>(nb_sc);
    k_scan3  <<<nb_N, TB>>>(batch, N);
    k_scatter<<<nb_E, TB>>>(src, dst, E);

    // layer 1
    k_gemm<1><<<(N + 127) / 128, TB>>>(x, W1, N);
    k_agg1   <<<(N * 32 + TB - 1) / TB, TB>>>(b1, N);

    // layer 2 + pool
    k_gemm<2><<<(N + 127) / 128, TB>>>(nullptr, W2, N);
    k_agg2   <<<(N * 16 + TB - 1) / TB, TB>>>(batch, b2, N);

    k_final<<<(NG * 64 + TB - 1) / TB, TB>>>(out);
}

// round 13
// speedup vs baseline: 1.3358x; 1.3358x over previous
#include <cuda_runtime.h>
#include <cuda_fp16.h>
#include <mma.h>
using namespace nvcuda;

#define NN 100000
#define NE 1600000
#define NG 64

// ---------------- scratch (device globals) ---------------------------------
__device__ float   g_dinv[NN];
__device__ int     g_deg[NN];
__device__ int     g_rowptr[NN];
__device__ int     g_cursor[NN];
__device__ int     g_bsum[128];
__device__ int     g_csr[NE];
__device__ __half2 g_h1p[(size_t)NN * 64];   // fp16: dinv * (x W1), 128 feat
__device__ float   g_h1 [(size_t)NN * 128];  // fp32: post agg+relu (gemm2 in)
__device__ __half2 g_h2p[(size_t)NN * 32];   // fp16: dinv * (h1 W2), 64 feat
__device__ float   g_gsum[NG * 64];
__device__ float   g_gcnt[NG];

__device__ __forceinline__ void red_add_v4(float* p, float4 v) {
    asm volatile("red.global.add.v4.f32 [%0], {%1, %2, %3, %4};"
                 :: "l"(p), "f"(v.x), "f"(v.y), "f"(v.z), "f"(v.w)
                 : "memory");
}
__device__ __forceinline__ float2 h2f(float raw) {
    return __half22float2(*reinterpret_cast<__half2*>(&raw));
}

// ---------------- init ------------------------------------------------------
__global__ void k_init(int n) {
    int i = blockIdx.x * blockDim.x + threadIdx.x;
    if (i < n)       g_deg[i] = 0;
    if (i < NG * 64) g_gsum[i] = 0.0f;
    if (i < NG)      g_gcnt[i] = 0.0f;
}

// ---------------- degree histogram over dst --------------------------------
__global__ void k_hist(const int* __restrict__ dst, int E) {
    int e = blockIdx.x * blockDim.x + threadIdx.x;
    if (e < E) atomicAdd(&g_deg[dst[e]], 1);
}

// ---------------- scan step 1: per-block (1024) scan -----------------------
__global__ void k_scan1(int n) {
    __shared__ int sh[1024];
    int tid = threadIdx.x;
    int i = blockIdx.x * 1024 + tid;
    int v = (i < n) ? g_deg[i] : 0;
    sh[tid] = v;
    __syncthreads();
#pragma unroll
    for (int off = 1; off < 1024; off <<= 1) {
        int t = (tid >= off) ? sh[tid - off] : 0;
        __syncthreads();
        sh[tid] += t;
        __syncthreads();
    }
    if (i < n) g_rowptr[i] = sh[tid] - v;          // exclusive
    if (tid == 1023) g_bsum[blockIdx.x] = sh[1023];
}

// ---------------- scan step 2: warp-shuffle scan of block sums -------------
__global__ void k_scan2(int nb) {
    int lane = threadIdx.x;   // 32 threads
    int carry = 0;
    for (int base = 0; base < nb; base += 32) {
        int idx = base + lane;
        int orig = (idx < nb) ? g_bsum[idx] : 0;
        int v = orig;
#pragma unroll
        for (int off = 1; off < 32; off <<= 1) {
            int u = __shfl_up_sync(0xFFFFFFFFu, v, off);
            if (lane >= off) v += u;
        }
        if (idx < nb) g_bsum[idx] = v - orig + carry;   // exclusive + carry
        carry += __shfl_sync(0xFFFFFFFFu, v, 31);
    }
}

// ---------------- scan step 3: offsets, cursor, dinv, graph counts ---------
__global__ void k_scan3(const int* __restrict__ batch, int n) {
    int i = blockIdx.x * blockDim.x + threadIdx.x;
    if (i < n) {
        int r = g_rowptr[i] + g_bsum[i >> 10];
        g_rowptr[i] = r;
        g_cursor[i] = r;
        g_dinv[i]   = rsqrtf((float)g_deg[i] + 1.0f);   // +1 self loop
        atomicAdd(&g_gcnt[batch[i]], 1.0f);
    }
}

// ---------------- CSR scatter ----------------------------------------------
__global__ void k_scatter(const int* __restrict__ src,
                          const int* __restrict__ dst, int E) {
    int e = blockIdx.x * blockDim.x + threadIdx.x;
    if (e < E) {
        int pos = atomicAdd(&g_cursor[dst[e]], 1);
        g_csr[pos] = src[e];
    }
}

// ---------------- TF32 GEMM (single pass): C = fp16((dinv*A) @ W) ----------
// A tf32-rounded (RNA) at smem-fill; B converted at smem-fill; one mma/k-step.
// LAYER 1: A = x, C = g_h1p, BN = 128.  LAYER 2: A = g_h1, C = g_h2p, BN = 64.
template <int LAYER>
__global__ void k_gemm(const float* __restrict__ Ain,
                       const float* __restrict__ W, int M) {
    constexpr int BN  = (LAYER == 1) ? 128 : 64;
    constexpr int K   = 128;
    constexpr int KC  = 32;
    constexpr int LDA = KC + 8;                 // 40, multiple of 4
    constexpr int LDB = BN + 8;                 // 136 / 72, multiple of 4
    constexpr int WN  = BN / 2;                 // 64 or 32
    constexpr int NF  = WN / 16;                // 4 or 2
    const float* __restrict__ A = (LAYER == 1) ? Ain : g_h1;
    __half2* __restrict__     C = (LAYER == 1) ? g_h1p : g_h2p;
    constexpr int CH2 = BN / 2;

    __shared__ __align__(16) float As[128][LDA];
    __shared__ __align__(16) float Bs[KC][LDB];

    const int t    = threadIdx.x;
    const int wid  = t >> 5;
    const int lane = t & 31;
    const int mbase = blockIdx.x * 128;
    const int wm = (wid >> 1) * 32;
    const int wn = (wid & 1) * WN;

    wmma::fragment<wmma::accumulator, 16, 16, 8, float> c[2][NF];
#pragma unroll
    for (int i = 0; i < 2; i++)
#pragma unroll
        for (int j = 0; j < NF; j++) wmma::fill_fragment(c[i][j], 0.0f);

    for (int k0 = 0; k0 < K; k0 += KC) {
        // A tile: 128 x 32 floats = 1024 float4, 4/thread; tf32-round here
#pragma unroll
        for (int j = 0; j < 4; j++) {
            int idx = t + j * 256;
            int row = idx >> 3;
            int kq  = (idx & 7) << 2;
            float4 av = make_float4(0.f, 0.f, 0.f, 0.f);
            float  s  = 0.0f;
            if (mbase + row < M) {
                av = *reinterpret_cast<const float4*>(
                    A + (size_t)(mbase + row) * K + k0 + kq);
                s = g_dinv[mbase + row];
            }
            As[row][kq + 0] = wmma::__float_to_tf32(s * av.x);
            As[row][kq + 1] = wmma::__float_to_tf32(s * av.y);
            As[row][kq + 2] = wmma::__float_to_tf32(s * av.z);
            As[row][kq + 3] = wmma::__float_to_tf32(s * av.w);
        }
        // B tile: KC x BN floats
        constexpr int B4  = KC * BN / 4;        // 1024 or 512
#pragma unroll
        for (int j = 0; j < B4 / 256; j++) {
            int idx = t + j * 256;
            int row = idx / (BN / 4);
            int col = (idx % (BN / 4)) << 2;
            float4 bv = *reinterpret_cast<const float4*>(
                W + (size_t)(k0 + row) * BN + col);
            Bs[row][col + 0] = wmma::__float_to_tf32(bv.x);
            Bs[row][col + 1] = wmma::__float_to_tf32(bv.y);
            Bs[row][col + 2] = wmma::__float_to_tf32(bv.z);
            Bs[row][col + 3] = wmma::__float_to_tf32(bv.w);
        }
        __syncthreads();

#pragma unroll
        for (int kk = 0; kk < KC; kk += 8) {
            wmma::fragment<wmma::matrix_a, 16, 16, 8, wmma::precision::tf32, wmma::row_major> a[2];
            wmma::fragment<wmma::matrix_b, 16, 16, 8, wmma::precision::tf32, wmma::row_major> b[NF];
#pragma unroll
            for (int i = 0; i < 2; i++)
                wmma::load_matrix_sync(a[i], &As[wm + i * 16][kk], LDA);
#pragma unroll
            for (int j = 0; j < NF; j++)
                wmma::load_matrix_sync(b[j], &Bs[kk][wn + j * 16], LDB);
#pragma unroll
            for (int i = 0; i < 2; i++)
#pragma unroll
                for (int j = 0; j < NF; j++)
                    wmma::mma_sync(c[i][j], a[i], b[j], c[i][j]);
        }
        __syncthreads();
    }

    // epilogue: reuse As as per-warp stage (16x20 floats each), emit half2
    float* stg = &As[0][0] + wid * 320;
#pragma unroll
    for (int i = 0; i < 2; i++)
#pragma unroll
        for (int j = 0; j < NF; j++) {
            wmma::store_matrix_sync(stg, c[i][j], 20, wmma::mem_row_major);
            __syncwarp();
#pragma unroll
            for (int it = 0; it < 4; it++) {
                int idx = lane + it * 32;            // 0..127
                int rr  = idx >> 3;                  // 0..15
                int cp  = idx & 7;                   // half2 col pair
                int m = mbase + wm + i * 16 + rr;
                if (m < M) {
                    __half2 hv = __floats2half2_rn(stg[rr * 20 + cp * 2],
                                                   stg[rr * 20 + cp * 2 + 1]);
                    C[(size_t)m * CH2 + wn / 2 + j * 8 + cp] = hv;
                }
            }
            __syncwarp();
        }
}

// ---------------- agg layer 1 (D=128): warp/node, fp16 gather, MLP=8 -------
__global__ void k_agg1(const float* __restrict__ b1, int N) {
    int w = (blockIdx.x * blockDim.x + threadIdx.x) >> 5;
    if (w >= N) return;
    int lane = threadIdx.x & 31;
    const float2* H = (const float2*)g_h1p;   // 32 float2 per row (=4 halves)

    int start = g_rowptr[w];
    int cnt   = g_deg[w];

    float2 raw = __ldg(H + (size_t)w * 32 + lane);    // self term
    float2 p0 = h2f(raw.x), p1 = h2f(raw.y);
    float4 acc = make_float4(p0.x, p0.y, p1.x, p1.y);

    int j = 0;
    for (; j + 8 <= cnt; j += 8) {
        int s[8]; float2 r[8];
#pragma unroll
        for (int q = 0; q < 8; q++) s[q] = __ldg(g_csr + start + j + q);
#pragma unroll
        for (int q = 0; q < 8; q++) r[q] = __ldg(H + (size_t)s[q] * 32 + lane);
#pragma unroll
        for (int q = 0; q < 8; q++) {
            float2 a0 = h2f(r[q].x), a1 = h2f(r[q].y);
            acc.x += a0.x; acc.y += a0.y; acc.z += a1.x; acc.w += a1.y;
        }
    }
    if (j + 4 <= cnt) {
        int s[4]; float2 r[4];
#pragma unroll
        for (int q = 0; q < 4; q++) s[q] = __ldg(g_csr + start + j + q);
#pragma unroll
        for (int q = 0; q < 4; q++) r[q] = __ldg(H + (size_t)s[q] * 32 + lane);
#pragma unroll
        for (int q = 0; q < 4; q++) {
            float2 a0 = h2f(r[q].x), a1 = h2f(r[q].y);
            acc.x += a0.x; acc.y += a0.y; acc.z += a1.x; acc.w += a1.y;
        }
        j += 4;
    }
    for (; j < cnt; j++) {
        int s = __ldg(g_csr + start + j);
        float2 r = __ldg(H + (size_t)s * 32 + lane);
        float2 a0 = h2f(r.x), a1 = h2f(r.y);
        acc.x += a0.x; acc.y += a0.y; acc.z += a1.x; acc.w += a1.y;
    }
    float di = g_dinv[w];
    float4 bb = __ldg((const float4*)b1 + lane);
    acc.x = fmaxf(di * acc.x + bb.x, 0.0f);
    acc.y = fmaxf(di * acc.y + bb.y, 0.0f);
    acc.z = fmaxf(di * acc.z + bb.z, 0.0f);
    acc.w = fmaxf(di * acc.w + bb.w, 0.0f);
    ((float4*)g_h1)[(size_t)w * 32 + lane] = acc;
}

// ---------------- agg layer 2 (D=64)+pool: 16 thr/node, fp16, MLP=8 --------
__global__ void k_agg2(const int* __restrict__ batch,
                       const float* __restrict__ b2, int N) {
    int idx = blockIdx.x * blockDim.x + threadIdx.x;
    int node = idx >> 4;
    if (node >= N) return;
    int f4 = idx & 15;
    const float2* H = (const float2*)g_h2p;   // 16 float2 per row

    int start = g_rowptr[node];
    int cnt   = g_deg[node];

    float2 raw = __ldg(H + (size_t)node * 16 + f4);   // self term
    float2 p0 = h2f(raw.x), p1 = h2f(raw.y);
    float4 acc = make_float4(p0.x, p0.y, p1.x, p1.y);

    int j = 0;
    for (; j + 8 <= cnt; j += 8) {
        int s[8]; float2 r[8];
#pragma unroll
        for (int q = 0; q < 8; q++) s[q] = __ldg(g_csr + start + j + q);
#pragma unroll
        for (int q = 0; q < 8; q++) r[q] = __ldg(H + (size_t)s[q] * 16 + f4);
#pragma unroll
        for (int q = 0; q < 8; q++) {
            float2 a0 = h2f(r[q].x), a1 = h2f(r[q].y);
            acc.x += a0.x; acc.y += a0.y; acc.z += a1.x; acc.w += a1.y;
        }
    }
    if (j + 4 <= cnt) {
        int s[4]; float2 r[4];
#pragma unroll
        for (int q = 0; q < 4; q++) s[q] = __ldg(g_csr + start + j + q);
#pragma unroll
        for (int q = 0; q < 4; q++) r[q] = __ldg(H + (size_t)s[q] * 16 + f4);
#pragma unroll
        for (int q = 0; q < 4; q++) {
            float2 a0 = h2f(r[q].x), a1 = h2f(r[q].y);
            acc.x += a0.x; acc.y += a0.y; acc.z += a1.x; acc.w += a1.y;
        }
        j += 4;
    }
    for (; j < cnt; j++) {
        int s = __ldg(g_csr + start + j);
        float2 r = __ldg(H + (size_t)s * 16 + f4);
        float2 a0 = h2f(r.x), a1 = h2f(r.y);
        acc.x += a0.x; acc.y += a0.y; acc.z += a1.x; acc.w += a1.y;
    }
    float di = g_dinv[node];
    float4 bb = __ldg((const float4*)b2 + f4);
    acc.x = fmaxf(di * acc.x + bb.x, 0.0f);
    acc.y = fmaxf(di * acc.y + bb.y, 0.0f);
    acc.z = fmaxf(di * acc.z + bb.z, 0.0f);
    acc.w = fmaxf(di * acc.w + bb.w, 0.0f);

    int g = __ldg(batch + node);
    red_add_v4(&g_gsum[(g << 6) + (f4 << 2)], acc);
}

// ---------------- mean -----------------------------------------------------
__global__ void k_final(float* __restrict__ out) {
    int i = blockIdx.x * blockDim.x + threadIdx.x;
    if (i < NG * 64) out[i] = g_gsum[i] / fmaxf(g_gcnt[i >> 6], 1.0f);
}

// ===========================================================================
extern "C" void kernel_launch(void* const* d_in, const int* in_sizes, int n_in,
                              void* d_out, int out_size) {
    const float* x     = (const float*)d_in[0];
    const int*   ei    = (const int*)d_in[1];
    const int*   batch = (const int*)d_in[2];
    const float* W1    = (const float*)d_in[3];
    const float* b1    = (const float*)d_in[4];
    const float* W2    = (const float*)d_in[5];
    const float* b2    = (const float*)d_in[6];
    float*       out   = (float*)d_out;

    const int N = in_sizes[2];        // 100000
    const int E = in_sizes[1] / 2;    // 1600000
    const int* src = ei;
    const int* dst = ei + E;

    const int TB = 256;
    int nb_N  = (N + TB - 1) / TB;
    int nb_E  = (E + TB - 1) / TB;
    int nb_sc = (N + 1023) / 1024;    // scan blocks

    // graph prep: degree, rowptr, csr, dinv, graph counts
    k_init   <<<nb_N, TB>>>(N);
    k_hist   <<<nb_E, TB>>>(dst, E);
    k_scan1  <<<nb_sc, 1024>>>(N);
    k_scan2  <<<1, 32>>>(nb_sc);
    k_scan3  <<<nb_N, TB>>>(batch, N);
    k_scatter<<<nb_E, TB>>>(src, dst, E);

    // layer 1
    k_gemm<1><<<(N + 127) / 128, TB>>>(x, W1, N);
    k_agg1   <<<(N * 32 + TB - 1) / TB, TB>>>(b1, N);

    // layer 2 + pool
    k_gemm<2><<<(N + 127) / 128, TB>>>(nullptr, W2, N);
    k_agg2   <<<(N * 16 + TB - 1) / TB, TB>>>(batch, b2, N);

    k_final<<<(NG * 64 + TB - 1) / TB, TB>>>(out);
}

// round 14
// speedup vs baseline: 1.4028x; 1.0501x over previous
#include <cuda_runtime.h>
#include <cuda_fp16.h>
#include <mma.h>
using namespace nvcuda;

#define NN 100000
#define NE 1600000
#define NG 64

// ---------------- scratch (device globals) ---------------------------------
__device__ float   g_dinv[NN];
__device__ int     g_deg[NN];
__device__ int     g_rowptr[NN];
__device__ int     g_cursor[NN];
__device__ int     g_bsum[128];
__device__ int     g_csr[NE];
__device__ __half2 g_h1p[(size_t)NN * 64];   // fp16: dinv * (x W1), 128 feat
__device__ __half2 g_h1h[(size_t)NN * 64];   // fp16: post agg+relu (gemm2 in)
__device__ __half2 g_h2p[(size_t)NN * 32];   // fp16: dinv * (h1 W2), 64 feat
__device__ float   g_gsum[NG * 64];
__device__ float   g_gcnt[NG];

__device__ __forceinline__ void red_add_v4(float* p, float4 v) {
    asm volatile("red.global.add.v4.f32 [%0], {%1, %2, %3, %4};"
                 :: "l"(p), "f"(v.x), "f"(v.y), "f"(v.z), "f"(v.w)
                 : "memory");
}
__device__ __forceinline__ float2 h2f(float raw) {
    return __half22float2(*reinterpret_cast<__half2*>(&raw));
}

// ---------------- init ------------------------------------------------------
__global__ void k_init(int n) {
    int i = blockIdx.x * blockDim.x + threadIdx.x;
    if (i < n)       g_deg[i] = 0;
    if (i < NG * 64) g_gsum[i] = 0.0f;
    if (i < NG)      g_gcnt[i] = 0.0f;
}

// ---------------- degree histogram over dst (4 edges/thread) ---------------
__global__ void k_hist(const int* __restrict__ dst, int E) {
    int i = blockIdx.x * blockDim.x + threadIdx.x;
    int e = i << 2;
    if (e + 4 <= E) {
        int4 d = __ldg((const int4*)dst + i);
        atomicAdd(&g_deg[d.x], 1);
        atomicAdd(&g_deg[d.y], 1);
        atomicAdd(&g_deg[d.z], 1);
        atomicAdd(&g_deg[d.w], 1);
    } else {
        for (; e < E; e++) atomicAdd(&g_deg[dst[e]], 1);
    }
}

// ---------------- scan step 1: per-block (1024) scan -----------------------
__global__ void k_scan1(int n) {
    __shared__ int sh[1024];
    int tid = threadIdx.x;
    int i = blockIdx.x * 1024 + tid;
    int v = (i < n) ? g_deg[i] : 0;
    sh[tid] = v;
    __syncthreads();
#pragma unroll
    for (int off = 1; off < 1024; off <<= 1) {
        int t = (tid >= off) ? sh[tid - off] : 0;
        __syncthreads();
        sh[tid] += t;
        __syncthreads();
    }
    if (i < n) g_rowptr[i] = sh[tid] - v;          // exclusive
    if (tid == 1023) g_bsum[blockIdx.x] = sh[1023];
}

// ---------------- scan step 2: warp-shuffle scan of block sums -------------
__global__ void k_scan2(int nb) {
    int lane = threadIdx.x;   // 32 threads
    int carry = 0;
    for (int base = 0; base < nb; base += 32) {
        int idx = base + lane;
        int orig = (idx < nb) ? g_bsum[idx] : 0;
        int v = orig;
#pragma unroll
        for (int off = 1; off < 32; off <<= 1) {
            int u = __shfl_up_sync(0xFFFFFFFFu, v, off);
            if (lane >= off) v += u;
        }
        if (idx < nb) g_bsum[idx] = v - orig + carry;   // exclusive + carry
        carry += __shfl_sync(0xFFFFFFFFu, v, 31);
    }
}

// ---------------- scan step 3: offsets, cursor, dinv, graph counts ---------
__global__ void k_scan3(const int* __restrict__ batch, int n) {
    int i = blockIdx.x * blockDim.x + threadIdx.x;
    if (i < n) {
        int r = g_rowptr[i] + g_bsum[i >> 10];
        g_rowptr[i] = r;
        g_cursor[i] = r;
        g_dinv[i]   = rsqrtf((float)g_deg[i] + 1.0f);   // +1 self loop
        atomicAdd(&g_gcnt[batch[i]], 1.0f);
    }
}

// ---------------- CSR scatter (4 edges/thread) -----------------------------
__global__ void k_scatter(const int* __restrict__ src,
                          const int* __restrict__ dst, int E) {
    int i = blockIdx.x * blockDim.x + threadIdx.x;
    int e = i << 2;
    if (e + 4 <= E) {
        int4 s4 = __ldg((const int4*)src + i);
        int4 d4 = __ldg((const int4*)dst + i);
        g_csr[atomicAdd(&g_cursor[d4.x], 1)] = s4.x;
        g_csr[atomicAdd(&g_cursor[d4.y], 1)] = s4.y;
        g_csr[atomicAdd(&g_cursor[d4.z], 1)] = s4.z;
        g_csr[atomicAdd(&g_cursor[d4.w], 1)] = s4.w;
    } else {
        for (; e < E; e++)
            g_csr[atomicAdd(&g_cursor[dst[e]], 1)] = src[e];
    }
}

// ---------------- TF32 GEMM (single pass): C = fp16((dinv*A) @ W) ----------
// LAYER 1: A = x (fp32 arg), C = g_h1p, BN = 128.
// LAYER 2: A = g_h1h (fp16),  C = g_h2p, BN = 64.
template <int LAYER>
__global__ void k_gemm(const float* __restrict__ Ain,
                       const float* __restrict__ W, int M) {
    constexpr int BN  = (LAYER == 1) ? 128 : 64;
    constexpr int K   = 128;
    constexpr int KC  = 32;
    constexpr int LDA = KC + 8;                 // 40, multiple of 4
    constexpr int LDB = BN + 8;                 // 136 / 72, multiple of 4
    constexpr int WN  = BN / 2;                 // 64 or 32
    constexpr int NF  = WN / 16;                // 4 or 2
    __half2* __restrict__ C = (LAYER == 1) ? g_h1p : g_h2p;
    constexpr int CH2 = BN / 2;

    __shared__ __align__(16) float As[128][LDA];
    __shared__ __align__(16) float Bs[KC][LDB];

    const int t    = threadIdx.x;
    const int wid  = t >> 5;
    const int lane = t & 31;
    const int mbase = blockIdx.x * 128;
    const int wm = (wid >> 1) * 32;
    const int wn = (wid & 1) * WN;

    wmma::fragment<wmma::accumulator, 16, 16, 8, float> c[2][NF];
#pragma unroll
    for (int i = 0; i < 2; i++)
#pragma unroll
        for (int j = 0; j < NF; j++) wmma::fill_fragment(c[i][j], 0.0f);

    for (int k0 = 0; k0 < K; k0 += KC) {
        if (LAYER == 1) {
            // A tile from fp32 x: 128 x 32 floats = 1024 float4, 4/thread
#pragma unroll
            for (int j = 0; j < 4; j++) {
                int idx = t + j * 256;
                int row = idx >> 3;
                int kq  = (idx & 7) << 2;
                float4 av = make_float4(0.f, 0.f, 0.f, 0.f);
                float  s  = 0.0f;
                if (mbase + row < M) {
                    av = *reinterpret_cast<const float4*>(
                        Ain + (size_t)(mbase + row) * K + k0 + kq);
                    s = g_dinv[mbase + row];
                }
                As[row][kq + 0] = wmma::__float_to_tf32(s * av.x);
                As[row][kq + 1] = wmma::__float_to_tf32(s * av.y);
                As[row][kq + 2] = wmma::__float_to_tf32(s * av.z);
                As[row][kq + 3] = wmma::__float_to_tf32(s * av.w);
            }
        } else {
            // A tile from fp16 h1h: 128 rows x 32 halves = 512 float4, 2/thread
#pragma unroll
            for (int j = 0; j < 2; j++) {
                int idx = t + j * 256;
                int row = idx >> 2;
                int c8  = (idx & 3) << 3;
                float4 av = make_float4(0.f, 0.f, 0.f, 0.f);
                float  s  = 0.0f;
                if (mbase + row < M) {
                    av = *((const float4*)g_h1h +
                           (size_t)(mbase + row) * 16 + (k0 >> 3) + (idx & 3));
                    s = g_dinv[mbase + row];
                }
                float2 f0 = h2f(av.x), f1 = h2f(av.y);
                float2 f2 = h2f(av.z), f3 = h2f(av.w);
                As[row][c8 + 0] = wmma::__float_to_tf32(s * f0.x);
                As[row][c8 + 1] = wmma::__float_to_tf32(s * f0.y);
                As[row][c8 + 2] = wmma::__float_to_tf32(s * f1.x);
                As[row][c8 + 3] = wmma::__float_to_tf32(s * f1.y);
                As[row][c8 + 4] = wmma::__float_to_tf32(s * f2.x);
                As[row][c8 + 5] = wmma::__float_to_tf32(s * f2.y);
                As[row][c8 + 6] = wmma::__float_to_tf32(s * f3.x);
                As[row][c8 + 7] = wmma::__float_to_tf32(s * f3.y);
            }
        }
        // B tile: KC x BN floats
        constexpr int B4  = KC * BN / 4;        // 1024 or 512
#pragma unroll
        for (int j = 0; j < B4 / 256; j++) {
            int idx = t + j * 256;
            int row = idx / (BN / 4);
            int col = (idx % (BN / 4)) << 2;
            float4 bv = *reinterpret_cast<const float4*>(
                W + (size_t)(k0 + row) * BN + col);
            Bs[row][col + 0] = wmma::__float_to_tf32(bv.x);
            Bs[row][col + 1] = wmma::__float_to_tf32(bv.y);
            Bs[row][col + 2] = wmma::__float_to_tf32(bv.z);
            Bs[row][col + 3] = wmma::__float_to_tf32(bv.w);
        }
        __syncthreads();

#pragma unroll
        for (int kk = 0; kk < KC; kk += 8) {
            wmma::fragment<wmma::matrix_a, 16, 16, 8, wmma::precision::tf32, wmma::row_major> a[2];
            wmma::fragment<wmma::matrix_b, 16, 16, 8, wmma::precision::tf32, wmma::row_major> b[NF];
#pragma unroll
            for (int i = 0; i < 2; i++)
                wmma::load_matrix_sync(a[i], &As[wm + i * 16][kk], LDA);
#pragma unroll
            for (int j = 0; j < NF; j++)
                wmma::load_matrix_sync(b[j], &Bs[kk][wn + j * 16], LDB);
#pragma unroll
            for (int i = 0; i < 2; i++)
#pragma unroll
                for (int j = 0; j < NF; j++)
                    wmma::mma_sync(c[i][j], a[i], b[j], c[i][j]);
        }
        __syncthreads();
    }

    // epilogue: reuse As as per-warp stage (16x20 floats each), emit half2
    float* stg = &As[0][0] + wid * 320;
#pragma unroll
    for (int i = 0; i < 2; i++)
#pragma unroll
        for (int j = 0; j < NF; j++) {
            wmma::store_matrix_sync(stg, c[i][j], 20, wmma::mem_row_major);
            __syncwarp();
#pragma unroll
            for (int it = 0; it < 4; it++) {
                int idx = lane + it * 32;            // 0..127
                int rr  = idx >> 3;                  // 0..15
                int cp  = idx & 7;                   // half2 col pair
                int m = mbase + wm + i * 16 + rr;
                if (m < M) {
                    __half2 hv = __floats2half2_rn(stg[rr * 20 + cp * 2],
                                                   stg[rr * 20 + cp * 2 + 1]);
                    C[(size_t)m * CH2 + wn / 2 + j * 8 + cp] = hv;
                }
            }
            __syncwarp();
        }
}

// ---------------- agg layer 1 (D=128): warp/node, 2 nbrs/iter, LDG.128 -----
// lanes 0-15 take even neighbors, 16-31 odd; each lane covers 8 features.
__global__ void k_agg1(const float* __restrict__ b1, int N) {
    int w = (blockIdx.x * blockDim.x + threadIdx.x) >> 5;
    if (w >= N) return;
    int lane = threadIdx.x & 31;
    int half = lane >> 4;                       // 0 or 1
    int l16  = lane & 15;
    const float4* H = (const float4*)g_h1p;     // 16 float4 per row (256B)

    int start = g_rowptr[w];
    int cnt   = g_deg[w];

    float acc[8];
#pragma unroll
    for (int q = 0; q < 8; q++) acc[q] = 0.0f;

    // self term (lower half only)
    if (half == 0) {
        float4 r = __ldg(H + (size_t)w * 16 + l16);
        float2 f0 = h2f(r.x), f1 = h2f(r.y), f2 = h2f(r.z), f3 = h2f(r.w);
        acc[0] = f0.x; acc[1] = f0.y; acc[2] = f1.x; acc[3] = f1.y;
        acc[4] = f2.x; acc[5] = f2.y; acc[6] = f3.x; acc[7] = f3.y;
    }

    int j = 0;
    for (; j + 8 <= cnt; j += 8) {              // 4 pairs in flight
        int s[4]; float4 r[4];
#pragma unroll
        for (int q = 0; q < 4; q++) s[q] = __ldg(g_csr + start + j + 2 * q + half);
#pragma unroll
        for (int q = 0; q < 4; q++) r[q] = __ldg(H + (size_t)s[q] * 16 + l16);
#pragma unroll
        for (int q = 0; q < 4; q++) {
            float2 f0 = h2f(r[q].x), f1 = h2f(r[q].y);
            float2 f2 = h2f(r[q].z), f3 = h2f(r[q].w);
            acc[0] += f0.x; acc[1] += f0.y; acc[2] += f1.x; acc[3] += f1.y;
            acc[4] += f2.x; acc[5] += f2.y; acc[6] += f3.x; acc[7] += f3.y;
        }
    }
    for (; j + 2 <= cnt; j += 2) {
        int s = __ldg(g_csr + start + j + half);
        float4 r = __ldg(H + (size_t)s * 16 + l16);
        float2 f0 = h2f(r.x), f1 = h2f(r.y), f2 = h2f(r.z), f3 = h2f(r.w);
        acc[0] += f0.x; acc[1] += f0.y; acc[2] += f1.x; acc[3] += f1.y;
        acc[4] += f2.x; acc[5] += f2.y; acc[6] += f3.x; acc[7] += f3.y;
    }
    if (j < cnt && half == 0) {                 // odd tail
        int s = __ldg(g_csr + start + j);
        float4 r = __ldg(H + (size_t)s * 16 + l16);
        float2 f0 = h2f(r.x), f1 = h2f(r.y), f2 = h2f(r.z), f3 = h2f(r.w);
        acc[0] += f0.x; acc[1] += f0.y; acc[2] += f1.x; acc[3] += f1.y;
        acc[4] += f2.x; acc[5] += f2.y; acc[6] += f3.x; acc[7] += f3.y;
    }

    // combine halves
#pragma unroll
    for (int q = 0; q < 8; q++)
        acc[q] += __shfl_xor_sync(0xFFFFFFFFu, acc[q], 16);

    if (half == 0) {
        float di = g_dinv[w];
        float4 bb0 = __ldg((const float4*)b1 + l16 * 2);
        float4 bb1 = __ldg((const float4*)b1 + l16 * 2 + 1);
        float v0 = fmaxf(di * acc[0] + bb0.x, 0.0f);
        float v1 = fmaxf(di * acc[1] + bb0.y, 0.0f);
        float v2 = fmaxf(di * acc[2] + bb0.z, 0.0f);
        float v3 = fmaxf(di * acc[3] + bb0.w, 0.0f);
        float v4 = fmaxf(di * acc[4] + bb1.x, 0.0f);
        float v5 = fmaxf(di * acc[5] + bb1.y, 0.0f);
        float v6 = fmaxf(di * acc[6] + bb1.z, 0.0f);
        float v7 = fmaxf(di * acc[7] + bb1.w, 0.0f);
        uint4 u;
        *reinterpret_cast<__half2*>(&u.x) = __floats2half2_rn(v0, v1);
        *reinterpret_cast<__half2*>(&u.y) = __floats2half2_rn(v2, v3);
        *reinterpret_cast<__half2*>(&u.z) = __floats2half2_rn(v4, v5);
        *reinterpret_cast<__half2*>(&u.w) = __floats2half2_rn(v6, v7);
        ((uint4*)g_h1h)[(size_t)w * 16 + l16] = u;
    }
}

// ---------------- agg layer 2 (D=64)+pool: 16 thr/node, fp16, MLP=8 --------
__global__ void k_agg2(const int* __restrict__ batch,
                       const float* __restrict__ b2, int N) {
    int idx = blockIdx.x * blockDim.x + threadIdx.x;
    int node = idx >> 4;
    if (node >= N) return;
    int f4 = idx & 15;
    const float2* H = (const float2*)g_h2p;   // 16 float2 per row

    int start = g_rowptr[node];
    int cnt   = g_deg[node];

    float2 raw = __ldg(H + (size_t)node * 16 + f4);   // self term
    float2 p0 = h2f(raw.x), p1 = h2f(raw.y);
    float4 acc = make_float4(p0.x, p0.y, p1.x, p1.y);

    int j = 0;
    for (; j + 8 <= cnt; j += 8) {
        int s[8]; float2 r[8];
#pragma unroll
        for (int q = 0; q < 8; q++) s[q] = __ldg(g_csr + start + j + q);
#pragma unroll
        for (int q = 0; q < 8; q++) r[q] = __ldg(H + (size_t)s[q] * 16 + f4);
#pragma unroll
        for (int q = 0; q < 8; q++) {
            float2 a0 = h2f(r[q].x), a1 = h2f(r[q].y);
            acc.x += a0.x; acc.y += a0.y; acc.z += a1.x; acc.w += a1.y;
        }
    }
    if (j + 4 <= cnt) {
        int s[4]; float2 r[4];
#pragma unroll
        for (int q = 0; q < 4; q++) s[q] = __ldg(g_csr + start + j + q);
#pragma unroll
        for (int q = 0; q < 4; q++) r[q] = __ldg(H + (size_t)s[q] * 16 + f4);
#pragma unroll
        for (int q = 0; q < 4; q++) {
            float2 a0 = h2f(r[q].x), a1 = h2f(r[q].y);
            acc.x += a0.x; acc.y += a0.y; acc.z += a1.x; acc.w += a1.y;
        }
        j += 4;
    }
    for (; j < cnt; j++) {
        int s = __ldg(g_csr + start + j);
        float2 r = __ldg(H + (size_t)s * 16 + f4);
        float2 a0 = h2f(r.x), a1 = h2f(r.y);
        acc.x += a0.x; acc.y += a0.y; acc.z += a1.x; acc.w += a1.y;
    }
    float di = g_dinv[node];
    float4 bb = __ldg((const float4*)b2 + f4);
    acc.x = fmaxf(di * acc.x + bb.x, 0.0f);
    acc.y = fmaxf(di * acc.y + bb.y, 0.0f);
    acc.z = fmaxf(di * acc.z + bb.z, 0.0f);
    acc.w = fmaxf(di * acc.w + bb.w, 0.0f);

    int g = __ldg(batch + node);
    red_add_v4(&g_gsum[(g << 6) + (f4 << 2)], acc);
}

// ---------------- mean -----------------------------------------------------
__global__ void k_final(float* __restrict__ out) {
    int i = blockIdx.x * blockDim.x + threadIdx.x;
    if (i < NG * 64) out[i] = g_gsum[i] / fmaxf(g_gcnt[i >> 6], 1.0f);
}

// ===========================================================================
extern "C" void kernel_launch(void* const* d_in, const int* in_sizes, int n_in,
                              void* d_out, int out_size) {
    const float* x     = (const float*)d_in[0];
    const int*   ei    = (const int*)d_in[1];
    const int*   batch = (const int*)d_in[2];
    const float* W1    = (const float*)d_in[3];
    const float* b1    = (const float*)d_in[4];
    const float* W2    = (const float*)d_in[5];
    const float* b2    = (const float*)d_in[6];
    float*       out   = (float*)d_out;

    const int N = in_sizes[2];        // 100000
    const int E = in_sizes[1] / 2;    // 1600000
    const int* src = ei;
    const int* dst = ei + E;

    const int TB = 256;
    int nb_N  = (N + TB - 1) / TB;
    int nb_E4 = ((E + 3) / 4 + TB - 1) / TB;
    int nb_sc = (N + 1023) / 1024;    // scan blocks

    // graph prep: degree, rowptr, csr, dinv, graph counts
    k_init   <<<nb_N, TB>>>(N);
    k_hist   <<<nb_E4, TB>>>(dst, E);
    k_scan1  <<<nb_sc, 1024>>>(N);
    k_scan2  <<<1, 32>>>(nb_sc);
    k_scan3  <<<nb_N, TB>>>(batch, N);
    k_scatter<<<nb_E4, TB>>>(src, dst, E);

    // layer 1
    k_gemm<1><<<(N + 127) / 128, TB>>>(x, W1, N);
    k_agg1   <<<(N * 32 + TB - 1) / TB, TB>>>(b1, N);

    // layer 2 + pool
    k_gemm<2><<<(N + 127) / 128, TB>>>(nullptr, W2, N);
    k_agg2   <<<(N * 16 + TB - 1) / TB, TB>>>(batch, b2, N);

    k_final<<<(NG * 64 + TB - 1) / TB, TB>>>(out);
}